// round 3
// baseline (speedup 1.0000x reference)
#include <cuda_runtime.h>

// ---------------------------------------------------------------------------
// B=1024, D=16384, K=8, NEG_RATIO=6 -> 48 negatives/row, SAMPLE_SEED=42
// JAX partitionable threefry (verified exact, rel_err = 0.0 in R1)
// ---------------------------------------------------------------------------
#define BB     1024
#define DD     16384
#define NNEG   48
#define CAP    1024          // candidate list capacity (expected ~383, sd ~19)
#define PRETH  250u          // static pre-threshold on top byte of noise bits
#define T      256
#define CH     8             // elements per thread per chunk (float4 x2 loads)
#define NCH    (DD / (T * CH))   // 8 chunks

__device__ float g_part[BB];

// ---------------------------------------------------------------------------
// threefry2x32, key=(0,42), counter=(0,f).  Round-adds forced to IMAD (fma
// pipe) via mad.lo.u32 with opaque 'one' to balance alu/fma pipes.
// ---------------------------------------------------------------------------
__device__ __forceinline__ unsigned rotl(unsigned v, int r) {
    return __funnelshift_l(v, v, r);
}

__device__ __forceinline__ unsigned noise_bits(unsigned f, unsigned one) {
    const unsigned K1 = 42u;
    const unsigned K2 = 42u ^ 0x1BD11BDAu;
    unsigned x0 = 0u;          // c0 + ks0 = 0
    unsigned x1 = f + K1;      // c1 + ks1
#define FADD(a, b) asm("mad.lo.u32 %0, %1, %2, %0;" : "+r"(a) : "r"(b), "r"(one))
#define R4(ra, rb, rc, rd)                           \
    { FADD(x0, x1); x1 = rotl(x1, ra) ^ x0;          \
      FADD(x0, x1); x1 = rotl(x1, rb) ^ x0;          \
      FADD(x0, x1); x1 = rotl(x1, rc) ^ x0;          \
      FADD(x0, x1); x1 = rotl(x1, rd) ^ x0; }
    R4(13, 15, 26, 6)
    x0 += K1;  x1 += K2 + 1u;
    R4(17, 29, 16, 24)
    x0 += K2;  x1 += 0u + 2u;
    R4(13, 15, 26, 6)
    x0 += 0u;  x1 += K1 + 3u;
    R4(17, 29, 16, 24)
    x0 += K1;  x1 += K2 + 4u;
    R4(13, 15, 26, 6)
    x0 += K2;  x1 += 0u + 5u;
#undef R4
#undef FADD
    return x0 ^ x1;            // partitionable scheme: out = o0 ^ o1
}

__device__ __forceinline__ float softplus_f(float x) {
    return fmaxf(x, 0.f) + log1pf(__expf(-fabsf(x)));
}

// ---------------------------------------------------------------------------
// Fused kernel: one block per row.
//   Pass A: threefry over the row; positive-term loss inline; candidates with
//           top byte >= PRETH collected into smem with FULL 23-bit key +
//           tie-break index (no recompute ever needed on the fast path).
//   Select: 6-bucket histogram of candidates -> cutoff bucket + rank r.
//   Accum:  sure winners (bucket > bsel) + exact rank of boundary bucket
//           (JAX top_k lower-index tie-break via (D-1-j) minor key).
// ---------------------------------------------------------------------------
__global__ void __launch_bounds__(T)
k_fused(const float* __restrict__ pred, const float* __restrict__ target,
        unsigned one) {
    __shared__ unsigned long long cand[CAP];   // ((bits>>9) << 14) | (D-1-j)
    __shared__ int histF[256];                 // fast path uses idx 250..255 only
    __shared__ float warpbuf[T / 32];
    __shared__ int s_cc, s_bsel, s_r, s_flag;

    const int row = blockIdx.x;
    const int tid = threadIdx.x;
    const unsigned rowbase = (unsigned)row * DD;
    const float* __restrict__ prow = pred + rowbase;
    const float* __restrict__ trow = target + rowbase;
    const unsigned full = 0xFFFFFFFFu;
    const unsigned lanelt = (1u << (tid & 31)) - 1u;

    if (tid < 32) {
        if (tid < 8) histF[248 + tid] = 0;     // only live buckets on fast path
        if (tid == 0) { s_cc = 0; s_flag = 0; }
    }
    __syncthreads();

    float acc = 0.f;

#pragma unroll 1
    for (int c = 0; c < NCH; c++) {
        const unsigned base = (unsigned)c * (T * CH) + (unsigned)tid * CH;
        float t[CH];
        *reinterpret_cast<float4*>(&t[0]) =
            *reinterpret_cast<const float4*>(trow + base);
        *reinterpret_cast<float4*>(&t[4]) =
            *reinterpret_cast<const float4*>(trow + base + 4);
#pragma unroll
        for (int q = 0; q < CH; q++) {
            const unsigned j = base + (unsigned)q;
            const unsigned bits = noise_bits(rowbase + j, one);
            const bool isp = (t[q] > 0.f);
            if (isp) acc += softplus_f(-prow[j]);          // positive BCE term
            const bool cnd = (!isp) && (bits >= (PRETH << 24));
            const unsigned m = __ballot_sync(full, cnd);
            if (m) {                                       // warp-uniform
                int bp = 0;
                if ((tid & 31) == 0) bp = atomicAdd(&s_cc, __popc(m));
                bp = __shfl_sync(full, bp, 0);
                if (cnd) {
                    const int p = bp + __popc(m & lanelt);
                    if (p < CAP)
                        cand[p] = (((unsigned long long)(bits >> 9)) << 14)
                                | (unsigned long long)(DD - 1u - j);
                }
            }
        }
    }
    __syncthreads();

    // --- select cutoff bucket among candidates (buckets 250..255) ---
    int C = min(s_cc, CAP);
    for (int i = tid; i < C; i += T)
        atomicAdd(&histF[(int)(cand[i] >> 29)], 1);
    __syncthreads();
    if (tid == 0) {
        int a = 0, bsel = -1, r = 0;
        for (int b = 255; b >= (int)PRETH; b--) {
            int h = histF[b];
            if (a + h >= NNEG) { bsel = b; r = NNEG - a; break; }
            a += h;
        }
        if (bsel < 0 || s_cc > CAP) s_flag = 1;   // never taken (fixed noise)
        else { s_bsel = bsel; s_r = r; }
    }
    __syncthreads();

    // --- exact fallback (astronomically unreachable; correctness insurance) ---
    if (s_flag) {
        for (int i = tid; i < 256; i += T) histF[i] = 0;
        if (tid == 0) s_cc = 0;
        __syncthreads();
        for (int j = tid; j < DD; j += T) {
            if (trow[j] > 0.f) continue;
            atomicAdd(&histF[noise_bits(rowbase + j, one) >> 24], 1);
        }
        __syncthreads();
        if (tid == 0) {
            int a = 0;
            for (int b = 255; b >= 0; b--) {
                int h = histF[b];
                if (a + h >= NNEG) { s_bsel = b; s_r = NNEG - a; break; }
                a += h;
            }
        }
        __syncthreads();
        const int bs = s_bsel;
        for (int j = tid; j < DD; j += T) {
            if (trow[j] > 0.f) continue;
            const unsigned bits = noise_bits(rowbase + j, one);
            const int b = (int)(bits >> 24);
            if (b > bs) acc += softplus_f(prow[j]);      // sure winner
            else if (b == bs) {
                int p = atomicAdd(&s_cc, 1);
                if (p < CAP)
                    cand[p] = (((unsigned long long)(bits >> 9)) << 14)
                            | (unsigned long long)(DD - 1u - j);
            }
        }
        __syncthreads();
        C = min(s_cc, CAP);
    }
    const int bsel = s_bsel;
    const int r = s_r;

    // --- accumulate: sure winners + exact rank in boundary bucket ---
    for (int i = tid; i < C; i += T) {
        const unsigned long long e = cand[i];
        const int b = (int)(e >> 29);
        const unsigned jj = DD - 1u - (unsigned)(e & 0x3FFFULL);
        if (b > bsel) {
            acc += softplus_f(prow[jj]);
        } else if (b == bsel) {
            int rank = 0;
            for (int u = 0; u < C; u++) {
                const unsigned long long o = cand[u];
                rank += ((int)(o >> 29) == bsel && o > e) ? 1 : 0;
            }
            if (rank < r)
                acc += softplus_f(prow[jj]);
        }
    }

    // --- block reduction -> per-row partial ---
    for (int off = 16; off; off >>= 1)
        acc += __shfl_down_sync(full, acc, off);
    if ((tid & 31) == 0) warpbuf[tid >> 5] = acc;
    __syncthreads();
    if (tid == 0) {
        float s = 0.f;
        for (int w = 0; w < T / 32; w++) s += warpbuf[w];
        g_part[row] = s;
    }
}

// ---------------------------------------------------------------------------
// Final reduction of 1024 row partials
// ---------------------------------------------------------------------------
__global__ void __launch_bounds__(256)
k_reduce(float* __restrict__ out) {
    __shared__ float warpbuf[8];
    float v = 0.f;
    for (int i = threadIdx.x; i < BB; i += 256) v += g_part[i];
    for (int off = 16; off; off >>= 1)
        v += __shfl_down_sync(0xFFFFFFFFu, v, off);
    if ((threadIdx.x & 31) == 0) warpbuf[threadIdx.x >> 5] = v;
    __syncthreads();
    if (threadIdx.x == 0) {
        float s = 0.f;
        for (int w = 0; w < 8; w++) s += warpbuf[w];
        out[0] = s;
    }
}

extern "C" void kernel_launch(void* const* d_in, const int* in_sizes, int n_in,
                              void* d_out, int out_size) {
    const float* pred   = (const float*)d_in[0];
    const float* target = (const float*)d_in[1];
    (void)in_sizes; (void)n_in; (void)out_size;

    k_fused<<<BB, T>>>(pred, target, 1u);
    k_reduce<<<1, 256>>>((float*)d_out);
}

// round 4
// speedup vs baseline: 1.7840x; 1.7840x over previous
#include <cuda_runtime.h>

// ---------------------------------------------------------------------------
// B=1024, D=16384, K=8, NEG_RATIO=6 -> 48 negatives/row, SAMPLE_SEED=42
// JAX partitionable threefry (verified exact: rel_err=0.0 in R1, 8e-8 in R3)
// ---------------------------------------------------------------------------
#define BB      1024
#define DD      16384
#define NTOT    (BB * DD)
#define NNEG    48
#define T       256
#define CH      8
#define ELEMS_PER_BLK (T * CH)            // 2048
#define NB1     (NTOT / ELEMS_PER_BLK)    // 8192 (8 blocks per row)
#define BLK_PER_ROW (DD / ELEMS_PER_BLK)  // 8
#define BCAP    64                        // per-block candidate cap (mean 16, sd 4)
#define CAP     512                       // per-row candidate cap (mean ~128)
#define THRESH  0xFE000000u               // P(candidate) = 1/128

__device__ unsigned long long g_cand[NB1 * BCAP];  // per-block candidate lists
__device__ int   g_bcnt[NB1];                      // per-block counts (bit31 = overflow)
__device__ float g_part1[NB1];                     // per-block positive-term partials
__device__ float g_part2[BB];                      // per-row totals

// ---------------------------------------------------------------------------
// threefry2x32, key=(0,42), counter=(0,f). All 30 adds forced to IMAD (fma
// pipe) via mad.lo.u32 with opaque 'one' so the alu pipe only carries SHF+LOP3.
// ---------------------------------------------------------------------------
__device__ __forceinline__ unsigned rotl(unsigned v, int r) {
    return __funnelshift_l(v, v, r);
}

__device__ __forceinline__ unsigned noise_bits(unsigned f, unsigned one) {
    const unsigned K1 = 42u;
    const unsigned K2 = 42u ^ 0x1BD11BDAu;
    unsigned x0 = 0u;
    unsigned x1 = f + K1;
#define FADD(a, b) asm("mad.lo.u32 %0, %1, %2, %0;" : "+r"(a) : "r"(b), "r"(one))
#define FADDI(a, imm) asm("mad.lo.u32 %0, %1, %2, %0;" : "+r"(a) : "r"(one), "n"(imm))
#define R4(ra, rb, rc, rd)                           \
    { FADD(x0, x1); x1 = rotl(x1, ra) ^ x0;          \
      FADD(x0, x1); x1 = rotl(x1, rb) ^ x0;          \
      FADD(x0, x1); x1 = rotl(x1, rc) ^ x0;          \
      FADD(x0, x1); x1 = rotl(x1, rd) ^ x0; }
    R4(13, 15, 26, 6)
    FADDI(x0, 42u);            FADDI(x1, (42u ^ 0x1BD11BDAu) + 1u);
    R4(17, 29, 16, 24)
    FADDI(x0, 42u ^ 0x1BD11BDAu); FADDI(x1, 2u);
    R4(13, 15, 26, 6)
    /* x0 += 0 */              FADDI(x1, 42u + 3u);
    R4(17, 29, 16, 24)
    FADDI(x0, 42u);            FADDI(x1, (42u ^ 0x1BD11BDAu) + 4u);
    R4(13, 15, 26, 6)
    FADDI(x0, 42u ^ 0x1BD11BDAu); FADDI(x1, 5u);
#undef R4
#undef FADD
#undef FADDI
    return x0 ^ x1;            // partitionable scheme
}

__device__ __forceinline__ float softplus_f(float x) {
    return fmaxf(x, 0.f) + log1pf(__expf(-fabsf(x)));
}

__device__ __forceinline__ unsigned long long pack_cand(unsigned bits, unsigned jloc) {
    return (((unsigned long long)(bits >> 9)) << 14)
         | (unsigned long long)(DD - 1u - jloc);      // minor key: lower j wins ties
}

// ---------------------------------------------------------------------------
// Kernel 1: threefry generation + positive-term loss + candidate compaction.
// One block = 2048 contiguous elements (1/8 of a row).
// ---------------------------------------------------------------------------
__global__ void __launch_bounds__(T)
k1_gen(const float* __restrict__ pred, const float* __restrict__ target,
       unsigned one) {
    __shared__ unsigned long long s_buf[BCAP];
    __shared__ float warpbuf[T / 32];
    __shared__ int s_cnt;

    const int tid = threadIdx.x;
    const unsigned gbase = blockIdx.x * (unsigned)ELEMS_PER_BLK + (unsigned)tid * CH;
    const unsigned jloc0 = gbase & (DD - 1u);

    if (tid == 0) s_cnt = 0;
    __syncthreads();

    float t[CH];
    *reinterpret_cast<float4*>(&t[0]) =
        *reinterpret_cast<const float4*>(target + gbase);
    *reinterpret_cast<float4*>(&t[4]) =
        *reinterpret_cast<const float4*>(target + gbase + 4);

    // straight-line: 8 independent threefry chains (compiler interleaves)
    unsigned b[CH];
#pragma unroll
    for (int q = 0; q < CH; q++) b[q] = noise_bits(gbase + (unsigned)q, one);

    float acc = 0.f;
#pragma unroll
    for (int q = 0; q < CH; q++) {
        if (t[q] > 0.f) {                                   // rare (8/16384)
            acc += softplus_f(-pred[gbase + (unsigned)q]);  // positive BCE term
        } else if (b[q] >= THRESH) {                        // rare (1/128)
            int p = atomicAdd(&s_cnt, 1);
            if (p < BCAP) s_buf[p] = pack_cand(b[q], jloc0 + (unsigned)q);
        }
    }

    // block reduction of positive-term partial
    for (int off = 16; off; off >>= 1)
        acc += __shfl_down_sync(0xFFFFFFFFu, acc, off);
    if ((tid & 31) == 0) warpbuf[tid >> 5] = acc;
    __syncthreads();

    const int cnt = s_cnt;
    const int n = min(cnt, BCAP);
    if (tid < n)
        g_cand[blockIdx.x * BCAP + tid] = s_buf[tid];
    if (tid == 0) {
        g_bcnt[blockIdx.x] = (cnt > BCAP) ? (n | (1 << 30)) : n;
        float s = 0.f;
        for (int w = 0; w < T / 32; w++) s += warpbuf[w];
        g_part1[blockIdx.x] = s;
    }
}

// ---------------------------------------------------------------------------
// Kernel 2: per-row exact top-48 among candidates (unique composite keys ->
// exact JAX top_k semantics), deterministic fixed-order summation.
// ---------------------------------------------------------------------------
__global__ void __launch_bounds__(T)
k2_select(const float* __restrict__ pred, const float* __restrict__ target,
          unsigned one) {
    __shared__ unsigned long long cand[CAP];
    __shared__ float sel[NNEG];
    __shared__ float posbuf[BLK_PER_ROW];
    __shared__ int s_bc[BLK_PER_ROW];
    __shared__ int hist[256];
    __shared__ int s_C, s_cb, s_cc;

    const int row = blockIdx.x;
    const int tid = threadIdx.x;
    const unsigned rowbase = (unsigned)row * DD;
    const float* __restrict__ prow = pred + rowbase;
    const float* __restrict__ trow = target + rowbase;

    if (tid < BLK_PER_ROW) {
        s_bc[tid]   = g_bcnt[row * BLK_PER_ROW + tid];
        posbuf[tid] = g_part1[row * BLK_PER_ROW + tid];
    }
    __syncthreads();

    bool bad = false;
    int offs[BLK_PER_ROW];
    {
        int a = 0;
#pragma unroll
        for (int i = 0; i < BLK_PER_ROW; i++) {
            int c = s_bc[i];
            if (c & (1 << 30)) bad = true;
            c &= 0xFFFF;
            offs[i] = a;
            a += c;
        }
        if (tid == 0) s_C = a;
    }
    __syncthreads();
    int C = s_C;
    if (C < NNEG || C > CAP) bad = true;

    if (!bad) {
        // gather the 8 sub-lists into smem
#pragma unroll
        for (int i = 0; i < BLK_PER_ROW; i++) {
            const int c = s_bc[i] & 0xFFFF;
            for (int k2i = tid; k2i < c; k2i += T)
                cand[offs[i] + k2i] =
                    g_cand[(row * BLK_PER_ROW + i) * BCAP + k2i];
        }
        __syncthreads();
    } else {
        // ---- exact fallback (never taken: noise field is fixed) ----
        for (int i = tid; i < 256; i += T) hist[i] = 0;
        if (tid == 0) s_cc = 0;
        __syncthreads();
        for (int j = tid; j < DD; j += T) {
            if (trow[j] > 0.f) continue;
            atomicAdd(&hist[noise_bits(rowbase + j, one) >> 24], 1);
        }
        __syncthreads();
        if (tid == 0) {
            int a = 0, cb = 0;
            for (int bkt = 255; bkt >= 0; bkt--) {
                a += hist[bkt];
                if (a >= NNEG) { cb = bkt; break; }
            }
            s_cb = cb;
        }
        __syncthreads();
        const unsigned cb = (unsigned)s_cb;
        for (int j = tid; j < DD; j += T) {
            if (trow[j] > 0.f) continue;
            const unsigned bits = noise_bits(rowbase + j, one);
            if ((bits >> 24) >= cb) {
                int p = atomicAdd(&s_cc, 1);
                if (p < CAP) cand[p] = pack_cand(bits, (unsigned)j);
            }
        }
        __syncthreads();
        C = min(s_cc, CAP);
    }

    // ---- exact rank among C candidates (keys unique: value major, index minor)
    for (int i = tid; i < C; i += T) {
        const unsigned long long e = cand[i];
        int rank = 0;
        for (int u = 0; u < C; u++) rank += (cand[u] > e) ? 1 : 0;
        if (rank < NNEG) {
            const unsigned j = DD - 1u - (unsigned)(e & 0x3FFFULL);
            sel[rank] = softplus_f(prow[j]);
        }
    }
    __syncthreads();

    if (tid == 0) {
        float s = 0.f;
#pragma unroll
        for (int i = 0; i < NNEG; i++) s += sel[i];          // fixed order
#pragma unroll
        for (int i = 0; i < BLK_PER_ROW; i++) s += posbuf[i];
        g_part2[row] = s;
    }
}

// ---------------------------------------------------------------------------
// Kernel 3: deterministic final reduction of 1024 row totals
// ---------------------------------------------------------------------------
__global__ void __launch_bounds__(256)
k3_reduce(float* __restrict__ out) {
    __shared__ float warpbuf[8];
    float v = 0.f;
    for (int i = threadIdx.x; i < BB; i += 256) v += g_part2[i];
    for (int off = 16; off; off >>= 1)
        v += __shfl_down_sync(0xFFFFFFFFu, v, off);
    if ((threadIdx.x & 31) == 0) warpbuf[threadIdx.x >> 5] = v;
    __syncthreads();
    if (threadIdx.x == 0) {
        float s = 0.f;
        for (int w = 0; w < 8; w++) s += warpbuf[w];
        out[0] = s;
    }
}

extern "C" void kernel_launch(void* const* d_in, const int* in_sizes, int n_in,
                              void* d_out, int out_size) {
    const float* pred   = (const float*)d_in[0];
    const float* target = (const float*)d_in[1];
    (void)in_sizes; (void)n_in; (void)out_size;

    k1_gen<<<NB1, T>>>(pred, target, 1u);
    k2_select<<<BB, T>>>(pred, target, 1u);
    k3_reduce<<<1, 256>>>((float*)d_out);
}